// round 17
// baseline (speedup 1.0000x reference)
#include <cuda_runtime.h>
#include <cuda_fp16.h>
#include <cstdint>

// ----------------------------------------------------------------------------
// VGG16 RoI head: pool -> fc6(relu) -> fc7(relu) -> {loc, score}
// R17: GEMMs moved to fp16 mma.sync.m16n8k16 + ldmatrix (fp32 accum).
// fp16 mantissa (10b, RN) == tf32 mantissa -> same error budget, 2x tensor
// rate and ~3x fewer issue slots per FLOP than the R16 tf32 kernel.
// Activations stored half end-to-end; weights converted at smem staging.
// ----------------------------------------------------------------------------

#define R_ROIS   300
#define CCH      512
#define HF       50
#define WF       50
#define NPOOL    (CCH * 49)          // 25088
#define NFC      4096
#define NLOC     84
#define NSCORE   21
#define NHEAD    (NLOC + NSCORE)     // 105
#define KSPLIT   16                  // heads split-K
#define GSPLIT   4                   // gemm split-K

// -------------------- device scratch (no allocations allowed) ---------------
__device__ __half g_pool_h[R_ROIS * NPOOL];          // ~15 MB
__device__ __half g_fc6_h [R_ROIS * NFC];            // ~2.5 MB
__device__ __half g_fc7_h [R_ROIS * NFC];            // ~2.5 MB
__device__ float  g_part  [GSPLIT * R_ROIS * NFC];   // ~19.7 MB fp32 partials
__device__ float  g_hpart [KSPLIT * R_ROIS * NHEAD]; // ~2.0 MB

// ------------------------------ PTX helpers ---------------------------------
__device__ __forceinline__ uint32_t pack_h2(float lo, float hi) {
    uint32_t r;
    asm("cvt.rn.f16x2.f32 %0, %1, %2;" : "=r"(r) : "f"(hi), "f"(lo));  // b->lo
    return r;
}

__device__ __forceinline__ void ldsm_x4(uint32_t& r0, uint32_t& r1,
                                        uint32_t& r2, uint32_t& r3, uint32_t addr) {
    asm volatile("ldmatrix.sync.aligned.m8n8.x4.shared.b16 {%0,%1,%2,%3}, [%4];"
                 : "=r"(r0), "=r"(r1), "=r"(r2), "=r"(r3) : "r"(addr));
}

__device__ __forceinline__ void ldsm_x4_trans(uint32_t& r0, uint32_t& r1,
                                              uint32_t& r2, uint32_t& r3, uint32_t addr) {
    asm volatile("ldmatrix.sync.aligned.m8n8.x4.trans.shared.b16 {%0,%1,%2,%3}, [%4];"
                 : "=r"(r0), "=r"(r1), "=r"(r2), "=r"(r3) : "r"(addr));
}

__device__ __forceinline__ void mma_f16(float c[4],
                                        uint32_t a0, uint32_t a1, uint32_t a2, uint32_t a3,
                                        uint32_t b0, uint32_t b1) {
    asm volatile(
        "mma.sync.aligned.m16n8k16.row.col.f32.f16.f16.f32 "
        "{%0,%1,%2,%3}, {%4,%5,%6,%7}, {%8,%9}, {%0,%1,%2,%3};"
        : "+f"(c[0]), "+f"(c[1]), "+f"(c[2]), "+f"(c[3])
        : "r"(a0), "r"(a1), "r"(a2), "r"(a3), "r"(b0), "r"(b1));
}

__device__ __forceinline__ void cp_async16(void* smem_dst, const void* gmem_src, bool pred) {
    uint32_t s = (uint32_t)__cvta_generic_to_shared(smem_dst);
    int sz = pred ? 16 : 0;  // src-size 0 => zero-fill 16B
    asm volatile("cp.async.cg.shared.global [%0], [%1], 16, %2;"
                 :: "r"(s), "l"(gmem_src), "r"(sz));
}

// ----------------------------- ROI max pool ---------------------------------
__global__ void roi_pool_kernel(const float* __restrict__ feat,
                                const float* __restrict__ rois,
                                __half* __restrict__ out)
{
    int idx = blockIdx.x * blockDim.x + threadIdx.x;
    if (idx >= R_ROIS * NPOOL) return;
    int r    = idx / NPOOL;
    int rem  = idx - r * NPOOL;
    int c    = rem / 49;
    int bin  = rem - c * 49;
    int by   = bin / 7;
    int bx   = bin - by * 7;

    int y1 = (int)(rois[r * 4 + 0] * 0.0625f);
    int x1 = (int)(rois[r * 4 + 1] * 0.0625f);
    int y2 = (int)(rois[r * 4 + 2] * 0.0625f);
    int x2 = (int)(rois[r * 4 + 3] * 0.0625f);
    int h = y2 - y1 + 1;
    int w = x2 - x1 + 1;

    int rs = y1 + (by * h) / 7;
    int re = y1 + ((by + 1) * h + 6) / 7;
    int cs = x1 + (bx * w) / 7;
    int ce = x1 + ((bx + 1) * w + 6) / 7;

    const float* fp = feat + c * (HF * WF);
    float m = -3.402823466e38f;
    for (int y = rs; y < re; ++y) {
        const float* rowp = fp + y * WF;
        for (int x = cs; x < ce; ++x)
            m = fmaxf(m, rowp[x]);
    }
    out[idx] = __float2half_rn(m);
}

// ------------------- fp16 mma.sync GEMM (fp32 accum) ------------------------
// Cpart[z][M,N] = A_half[M, zKP:(z+1)KP] @ B_f32[zKP:(z+1)KP, N]
// Block tile 64x128, BK=32, 4 warps (2x2), warp tile 32x64.
// A: cp.async (half, 2x16B/thread). B: LDG float4 -> cvt f16x2 -> STS.128,
// register double-buffered. ldmatrix fragments, 2-stage smem pipeline.
#define BM 64
#define BN 128
#define BK 32
#define AROW_H 40    // padded halves per A row (80B: banks 20r%32 all distinct)
#define BROW_H 136   // padded halves per B k-row (272B: banks 68k%32 distinct)

__global__ __launch_bounds__(128, 3)
void gemm_f16_kernel(const __half* __restrict__ A,
                     const float* __restrict__ B,
                     float* __restrict__ Cpart,
                     int M, int N, int ldA, int KP)
{
    __shared__ __align__(16) __half As[2][BM * AROW_H];
    __shared__ __align__(16) __half Bs[2][BK * BROW_H];

    const int tid  = threadIdx.x;
    const int m0   = blockIdx.y * BM;
    const int n0   = blockIdx.x * BN;
    const int z    = blockIdx.z;
    const int k0   = z * KP;          // in elements (half for A, rows for B)
    const int warp = tid >> 5;
    const int lane = tid & 31;
    const int wm   = warp >> 1;       // 0..1
    const int wn   = warp & 1;        // 0..1
    const int g    = lane >> 2;       // 0..7
    const int tg   = lane & 3;        // 0..3

    // A staging: 256 16B-chunks; thread t handles chunks t and t+128
    const int ar0 = tid >> 2;               // row of chunk t      (0..31)
    const int ac0 = tid & 3;                // 16B chunk in row
    const int ar1 = ar0 + 32;               // row of chunk t+128
    const bool ap0 = (m0 + ar0) < M;
    const bool ap1 = (m0 + ar1) < M;
    const __half* Ag0 = A + (size_t)(m0 + ar0) * ldA + k0 + ac0 * 8;
    const __half* Ag1 = A + (size_t)(m0 + ar1) * ldA + k0 + ac0 * 8;

    // B staging: thread t -> k-row = t>>2 (0..31), n-block = t&3 (32 floats)
    const int bkr = tid >> 2;
    const int bnb = tid & 3;
    const float* Bg = B + (size_t)(k0 + bkr) * N + n0 + bnb * 32;

    float acc[2][8][4];
    #pragma unroll
    for (int mi = 0; mi < 2; ++mi)
        #pragma unroll
        for (int ni = 0; ni < 8; ++ni)
            #pragma unroll
            for (int q = 0; q < 4; ++q) acc[mi][ni][q] = 0.0f;

    const int T = KP / BK;
    float4 bR[8];

    // ---- prologue: LDG B(0), cp.async A(0)
    #pragma unroll
    for (int j = 0; j < 8; ++j)
        bR[j] = *(const float4*)(Bg + j * 4);
    cp_async16(&As[0][ar0 * AROW_H + ac0 * 8], Ag0, ap0);
    cp_async16(&As[0][ar1 * AROW_H + ac0 * 8], Ag1, ap1);
    asm volatile("cp.async.commit_group;");

    const uint32_t AsBase = (uint32_t)__cvta_generic_to_shared(&As[0][0]);
    const uint32_t BsBase = (uint32_t)__cvta_generic_to_shared(&Bs[0][0]);
    const uint32_t AbufSz = BM * AROW_H * 2;
    const uint32_t BbufSz = BK * BROW_H * 2;

    for (int t = 0; t < T; ++t) {
        const int buf = t & 1;

        // STS B(t): bR -> Bs[buf] as half (pairs -> f16x2, 4x STS.128)
        {
            __half* brow = &Bs[buf][bkr * BROW_H + bnb * 32];
            #pragma unroll
            for (int j2 = 0; j2 < 4; ++j2) {
                float4 lo = bR[2 * j2], hi = bR[2 * j2 + 1];
                uint4 v;
                v.x = pack_h2(lo.x, lo.y);
                v.y = pack_h2(lo.z, lo.w);
                v.z = pack_h2(hi.x, hi.y);
                v.w = pack_h2(hi.z, hi.w);
                *(uint4*)(brow + j2 * 8) = v;
            }
        }
        // LDG B(t+1)
        if (t + 1 < T) {
            const float* Bgn = Bg + (size_t)(t + 1) * BK * N;
            #pragma unroll
            for (int j = 0; j < 8; ++j)
                bR[j] = *(const float4*)(Bgn + j * 4);
        }
        // drain this warp's A(t) copies, then make everything visible
        asm volatile("cp.async.wait_group 0;");
        __syncthreads();

        // issue A(t+1) into the other buffer (its readers finished pre-barrier)
        if (t + 1 < T) {
            const int nb = buf ^ 1;
            const size_t ka = (size_t)(t + 1) * BK;
            cp_async16(&As[nb][ar0 * AROW_H + ac0 * 8], Ag0 + ka, ap0);
            cp_async16(&As[nb][ar1 * AROW_H + ac0 * 8], Ag1 + ka, ap1);
            asm volatile("cp.async.commit_group;");
        }

        // ---- compute on As[buf], Bs[buf]
        const uint32_t Ab = AsBase + buf * AbufSz;
        const uint32_t Bb = BsBase + buf * BbufSz;
        #pragma unroll
        for (int kk = 0; kk < BK; kk += 16) {
            uint32_t a[2][4];
            #pragma unroll
            for (int mi = 0; mi < 2; ++mi) {
                const int rowA = wm * 32 + mi * 16 + (lane & 15);
                const int colA = kk + ((lane >> 4) << 3);
                ldsm_x4(a[mi][0], a[mi][1], a[mi][2], a[mi][3],
                        Ab + (rowA * AROW_H + colA) * 2);
            }
            #pragma unroll
            for (int nb = 0; nb < 4; ++nb) {
                uint32_t b0, b1, b2, b3;
                const int krow = kk + (lane & 15);
                const int ncol = wn * 64 + nb * 16 + ((lane >> 4) << 3);
                ldsm_x4_trans(b0, b1, b2, b3, Bb + (krow * BROW_H + ncol) * 2);
                #pragma unroll
                for (int mi = 0; mi < 2; ++mi) {
                    mma_f16(acc[mi][2 * nb],     a[mi][0], a[mi][1], a[mi][2], a[mi][3], b0, b1);
                    mma_f16(acc[mi][2 * nb + 1], a[mi][0], a[mi][1], a[mi][2], a[mi][3], b2, b3);
                }
            }
        }
    }

    // raw fp32 partial store
    float* Cz = Cpart + (size_t)z * M * N;
    #pragma unroll
    for (int mi = 0; mi < 2; ++mi) {
        #pragma unroll
        for (int ni = 0; ni < 8; ++ni) {
            const int row0 = m0 + wm * 32 + mi * 16 + g;
            const int col  = n0 + wn * 64 + ni * 8 + 2 * tg;
            if (row0 < M) {
                Cz[(size_t)row0 * N + col]     = acc[mi][ni][0];
                Cz[(size_t)row0 * N + col + 1] = acc[mi][ni][1];
            }
            if (row0 + 8 < M) {
                Cz[(size_t)(row0 + 8) * N + col]     = acc[mi][ni][2];
                Cz[(size_t)(row0 + 8) * N + col + 1] = acc[mi][ni][3];
            }
        }
    }
}

// reduce GSPLIT fp32 partials + bias + relu -> half (RN = the dtype rounding)
__global__ void gemm_reduce_kernel(const float* __restrict__ part,
                                   const float* __restrict__ bias,
                                   __half* __restrict__ C,
                                   int M, int N)
{
    int idx = blockIdx.x * blockDim.x + threadIdx.x;
    if (idx >= M * N) return;
    const int col = idx % N;
    const size_t stride = (size_t)M * N;
    float s = part[idx];
    #pragma unroll
    for (int p = 1; p < GSPLIT; ++p)
        s += part[p * stride + idx];   // fixed order: deterministic
    C[idx] = __float2half_rn(fmaxf(s + bias[col], 0.0f));
}

// ------------------------------- heads (fp32) -------------------------------
#define HKW (NFC / KSPLIT)   // 256
__global__ __launch_bounds__(128)
void heads_part_kernel(const __half* __restrict__ fc7,
                       const float* __restrict__ Wl,
                       const float* __restrict__ Ws,
                       float* __restrict__ part)
{
    __shared__ float Ash[4][HKW];
    const int t  = threadIdx.x;
    const int kp = blockIdx.x;
    const int k0 = kp * HKW;
    const int r0 = blockIdx.y * 4;

    // stage fc7[r0..r0+3][k0..k0+HKW): 8 halves per thread
    {
        const int j = t >> 5;            // roi 0..3
        const int i = t & 31;            // uint4 index (8 halves each)
        union { uint4 v; __half h[8]; } u;
        u.v = *(const uint4*)(fc7 + (size_t)(r0 + j) * NFC + k0 + i * 8);
        #pragma unroll
        for (int m = 0; m < 8; ++m)
            Ash[j][i * 8 + m] = __half2float(u.h[m]);
    }
    __syncthreads();

    if (t < NHEAD) {
        const float* Wp; int ldw, col;
        if (t < NLOC) { Wp = Wl; ldw = NLOC;   col = t; }
        else          { Wp = Ws; ldw = NSCORE; col = t - NLOC; }
        const float* wptr = Wp + (size_t)k0 * ldw + col;

        float a0 = 0.f, a1 = 0.f, a2 = 0.f, a3 = 0.f;
        #pragma unroll 8
        for (int k = 0; k < HKW; ++k) {
            const float w = __ldg(wptr + (size_t)k * ldw);
            a0 = fmaf(Ash[0][k], w, a0);
            a1 = fmaf(Ash[1][k], w, a1);
            a2 = fmaf(Ash[2][k], w, a2);
            a3 = fmaf(Ash[3][k], w, a3);
        }
        float* pp = part + (size_t)kp * (R_ROIS * NHEAD) + (size_t)r0 * NHEAD + t;
        pp[0 * NHEAD] = a0;
        pp[1 * NHEAD] = a1;
        pp[2 * NHEAD] = a2;
        pp[3 * NHEAD] = a3;
    }
}

__global__ void heads_reduce_kernel(const float* __restrict__ part,
                                    const float* __restrict__ bl,
                                    const float* __restrict__ bs,
                                    float* __restrict__ out)
{
    int idx = blockIdx.x * blockDim.x + threadIdx.x;
    if (idx >= R_ROIS * NHEAD) return;
    float s = 0.f;
    #pragma unroll
    for (int p = 0; p < KSPLIT; ++p)
        s += part[(size_t)p * (R_ROIS * NHEAD) + idx];
    const int roi = idx / NHEAD;
    const int c   = idx - roi * NHEAD;
    if (c < NLOC)
        out[(size_t)roi * NLOC + c] = s + bl[c];
    else
        out[(size_t)R_ROIS * NLOC + (size_t)roi * NSCORE + (c - NLOC)] = s + bs[c - NLOC];
}

// ------------------------------- launch -------------------------------------
extern "C" void kernel_launch(void* const* d_in, const int* in_sizes, int n_in,
                              void* d_out, int out_size)
{
    (void)in_sizes; (void)n_in; (void)out_size;
    const float* x     = (const float*)d_in[0];
    const float* rois  = (const float*)d_in[1];
    const float* W6    = (const float*)d_in[2];
    const float* b6    = (const float*)d_in[3];
    const float* W7    = (const float*)d_in[4];
    const float* b7    = (const float*)d_in[5];
    const float* Wl    = (const float*)d_in[6];
    const float* bl    = (const float*)d_in[7];
    const float* Ws    = (const float*)d_in[8];
    const float* bs    = (const float*)d_in[9];
    float* out = (float*)d_out;

    __half *pool_p, *fc6_p, *fc7_p;
    float *part_p, *hpart_p;
    cudaGetSymbolAddress((void**)&pool_p,  g_pool_h);
    cudaGetSymbolAddress((void**)&fc6_p,   g_fc6_h);
    cudaGetSymbolAddress((void**)&fc7_p,   g_fc7_h);
    cudaGetSymbolAddress((void**)&part_p,  g_part);
    cudaGetSymbolAddress((void**)&hpart_p, g_hpart);

    // 1) ROI adaptive maxpool -> half
    {
        const int total = R_ROIS * NPOOL;
        roi_pool_kernel<<<(total + 255) / 256, 256>>>(x, rois, pool_p);
    }
    // 2) fc6 = relu(pool @ W6 + b6)   M=300 N=4096 K=25088, split-K=4
    {
        dim3 grid(NFC / BN, (R_ROIS + BM - 1) / BM, GSPLIT);   // (32, 5, 4)
        gemm_f16_kernel<<<grid, 128>>>(pool_p, W6, part_p,
                                       R_ROIS, NFC, NPOOL, NPOOL / GSPLIT);
        const int tot = R_ROIS * NFC;
        gemm_reduce_kernel<<<(tot + 255) / 256, 256>>>(part_p, b6, fc6_p, R_ROIS, NFC);
    }
    // 3) fc7 = relu(fc6 @ W7 + b7)    M=300 N=4096 K=4096, split-K=4
    {
        dim3 grid(NFC / BN, (R_ROIS + BM - 1) / BM, GSPLIT);
        gemm_f16_kernel<<<grid, 128>>>(fc6_p, W7, part_p,
                                       R_ROIS, NFC, NFC, NFC / GSPLIT);
        const int tot = R_ROIS * NFC;
        gemm_reduce_kernel<<<(tot + 255) / 256, 256>>>(part_p, b7, fc7_p, R_ROIS, NFC);
    }
    // 4) heads: split-K=16 partials + deterministic reduce
    {
        dim3 grid(KSPLIT, R_ROIS / 4);
        heads_part_kernel<<<grid, 128>>>(fc7_p, Wl, Ws, hpart_p);
        heads_reduce_kernel<<<(R_ROIS * NHEAD + 255) / 256, 256>>>(hpart_p, bl, bs, out);
    }
}